// round 1
// baseline (speedup 1.0000x reference)
#include <cuda_runtime.h>
#include <stdint.h>

#define NTOK 65536
#define DIM  512
#define NQ   (NTOK * DIM)

// ---------------- scratch (device globals; no allocation) ----------------
__device__ float g_tf[NQ];
__device__ float g_ef[NQ];
__device__ float g_df[NQ];
__device__ float g_res[NQ];
__device__ float g_sqA[4 * NTOK];                 // rowsumsq of tf, ef, df, res
__device__ float g_cbsq[512 + 256 + 512 + 512];   // codebook sumsq (offsets 0,512,768,1280)
__device__ int   g_idx[4 * NTOK];                 // t, e, d0, d1
__device__ float g_P[(512 + 256 + 512 + 512) * DIM]; // projected codebooks
__device__ double g_losspart[4096];

// =====================================================================
// GEMM: C[m][n] = sum_k A[m*lda+k] * W[n*ldw+k] (+ bias[n])
// BM=64, BN=128, BK=16, 256 threads, per-thread 4x8. All dims divide tiles.
// =====================================================================
__global__ __launch_bounds__(256)
void gemm_nt(const float* __restrict__ A, int lda,
             const float* __restrict__ W, int ldw,
             const float* __restrict__ bias,
             float* __restrict__ C, int ldc, int Kin)
{
    __shared__ alignas(16) float sA[2][16][68];
    __shared__ alignas(16) float sB[2][16][132];
    const int tid = threadIdx.x;
    const int bm = blockIdx.y * 64;
    const int bn = blockIdx.x * 128;
    const int tx = tid & 15, ty = tid >> 4;

    const int arow = tid >> 2, akq = (tid & 3) << 2;   // A: 64x16, one f4/thread
    const int bcol0 = arow, bcol1 = arow + 64;         // B: 128x16, two f4/thread

    const float* Ap  = A + (size_t)(bm + arow) * lda + akq;
    const float* Wp0 = W + (size_t)(bn + bcol0) * ldw + akq;
    const float* Wp1 = W + (size_t)(bn + bcol1) * ldw + akq;

    float4 pa  = *(const float4*)Ap;
    float4 pb0 = *(const float4*)Wp0;
    float4 pb1 = *(const float4*)Wp1;
    sA[0][akq + 0][arow] = pa.x;  sA[0][akq + 1][arow] = pa.y;
    sA[0][akq + 2][arow] = pa.z;  sA[0][akq + 3][arow] = pa.w;
    sB[0][akq + 0][bcol0] = pb0.x; sB[0][akq + 1][bcol0] = pb0.y;
    sB[0][akq + 2][bcol0] = pb0.z; sB[0][akq + 3][bcol0] = pb0.w;
    sB[0][akq + 0][bcol1] = pb1.x; sB[0][akq + 1][bcol1] = pb1.y;
    sB[0][akq + 2][bcol1] = pb1.z; sB[0][akq + 3][bcol1] = pb1.w;
    __syncthreads();

    float acc[4][8];
#pragma unroll
    for (int i = 0; i < 4; i++)
#pragma unroll
        for (int j = 0; j < 8; j++) acc[i][j] = 0.f;

    const int nk = Kin >> 4;
    for (int t = 0; t < nk; ++t) {
        const int cur = t & 1;
        if (t + 1 < nk) {
            pa  = *(const float4*)(Ap  + (t + 1) * 16);
            pb0 = *(const float4*)(Wp0 + (t + 1) * 16);
            pb1 = *(const float4*)(Wp1 + (t + 1) * 16);
        }
#pragma unroll
        for (int kk = 0; kk < 16; ++kk) {
            float4 fa  = *(const float4*)&sA[cur][kk][ty << 2];
            float4 fb0 = *(const float4*)&sB[cur][kk][tx << 3];
            float4 fb1 = *(const float4*)&sB[cur][kk][(tx << 3) + 4];
            float av[4] = {fa.x, fa.y, fa.z, fa.w};
            float bv[8] = {fb0.x, fb0.y, fb0.z, fb0.w, fb1.x, fb1.y, fb1.z, fb1.w};
#pragma unroll
            for (int i = 0; i < 4; i++)
#pragma unroll
                for (int j = 0; j < 8; j++) acc[i][j] += av[i] * bv[j];
        }
        if (t + 1 < nk) {
            const int nxt = cur ^ 1;
            sA[nxt][akq + 0][arow] = pa.x;  sA[nxt][akq + 1][arow] = pa.y;
            sA[nxt][akq + 2][arow] = pa.z;  sA[nxt][akq + 3][arow] = pa.w;
            sB[nxt][akq + 0][bcol0] = pb0.x; sB[nxt][akq + 1][bcol0] = pb0.y;
            sB[nxt][akq + 2][bcol0] = pb0.z; sB[nxt][akq + 3][bcol0] = pb0.w;
            sB[nxt][akq + 0][bcol1] = pb1.x; sB[nxt][akq + 1][bcol1] = pb1.y;
            sB[nxt][akq + 2][bcol1] = pb1.z; sB[nxt][akq + 3][bcol1] = pb1.w;
        }
        __syncthreads();
    }

#pragma unroll
    for (int i = 0; i < 4; i++) {
        const int m = bm + (ty << 2) + i;
        float* Cr = C + (size_t)m * ldc + bn + (tx << 3);
#pragma unroll
        for (int j = 0; j < 8; j++) {
            float v = acc[i][j];
            if (bias) v += bias[bn + (tx << 3) + j];
            Cr[j] = v;
        }
    }
}

// =====================================================================
// Fused VQ: distances + argmin with reference-matching rounding.
// d = fl(fl(Asq + cbsq) - fl(2*dot)); tiebreak = lowest index
// (packed u64: [d bits | col], d>0 so float-bit order == value order).
// Block owns 64 rows x ALL codes (col passes of 128).
// =====================================================================
__global__ __launch_bounds__(256)
void vq_argmin(const float* __restrict__ A,
               const float* __restrict__ Asq,
               const float* __restrict__ cb,
               const float* __restrict__ cbsq,
               int Kcodes, int* __restrict__ outIdx)
{
    __shared__ alignas(16) float sA[2][16][68];
    __shared__ alignas(16) float sB[2][16][132];
    __shared__ unsigned long long sBest[64];
    const int tid = threadIdx.x;
    if (tid < 64) sBest[tid] = 0xFFFFFFFFFFFFFFFFULL;
    const int bm = blockIdx.x * 64;
    const int tx = tid & 15, ty = tid >> 4;
    const int arow = tid >> 2, akq = (tid & 3) << 2;
    const int bcol0 = arow, bcol1 = arow + 64;
    const float* Ap = A + (size_t)(bm + arow) * 512 + akq;
    __syncthreads();

    const int npass = Kcodes >> 7;
    for (int cp = 0; cp < npass; ++cp) {
        const int bn = cp << 7;
        const float* Bp0 = cb + (size_t)(bn + bcol0) * 512 + akq;
        const float* Bp1 = cb + (size_t)(bn + bcol1) * 512 + akq;

        float4 pa  = *(const float4*)Ap;
        float4 pb0 = *(const float4*)Bp0;
        float4 pb1 = *(const float4*)Bp1;
        sA[0][akq + 0][arow] = pa.x;  sA[0][akq + 1][arow] = pa.y;
        sA[0][akq + 2][arow] = pa.z;  sA[0][akq + 3][arow] = pa.w;
        sB[0][akq + 0][bcol0] = pb0.x; sB[0][akq + 1][bcol0] = pb0.y;
        sB[0][akq + 2][bcol0] = pb0.z; sB[0][akq + 3][bcol0] = pb0.w;
        sB[0][akq + 0][bcol1] = pb1.x; sB[0][akq + 1][bcol1] = pb1.y;
        sB[0][akq + 2][bcol1] = pb1.z; sB[0][akq + 3][bcol1] = pb1.w;
        __syncthreads();

        float acc[4][8];
#pragma unroll
        for (int i = 0; i < 4; i++)
#pragma unroll
            for (int j = 0; j < 8; j++) acc[i][j] = 0.f;

        for (int t = 0; t < 32; ++t) {   // Kin = 512 fixed
            const int cur = t & 1;
            if (t + 1 < 32) {
                pa  = *(const float4*)(Ap  + (t + 1) * 16);
                pb0 = *(const float4*)(Bp0 + (t + 1) * 16);
                pb1 = *(const float4*)(Bp1 + (t + 1) * 16);
            }
#pragma unroll
            for (int kk = 0; kk < 16; ++kk) {
                float4 fa  = *(const float4*)&sA[cur][kk][ty << 2];
                float4 fb0 = *(const float4*)&sB[cur][kk][tx << 3];
                float4 fb1 = *(const float4*)&sB[cur][kk][(tx << 3) + 4];
                float av[4] = {fa.x, fa.y, fa.z, fa.w};
                float bv[8] = {fb0.x, fb0.y, fb0.z, fb0.w, fb1.x, fb1.y, fb1.z, fb1.w};
#pragma unroll
                for (int i = 0; i < 4; i++)
#pragma unroll
                    for (int j = 0; j < 8; j++) acc[i][j] += av[i] * bv[j];
            }
            if (t + 1 < 32) {
                const int nxt = cur ^ 1;
                sA[nxt][akq + 0][arow] = pa.x;  sA[nxt][akq + 1][arow] = pa.y;
                sA[nxt][akq + 2][arow] = pa.z;  sA[nxt][akq + 3][arow] = pa.w;
                sB[nxt][akq + 0][bcol0] = pb0.x; sB[nxt][akq + 1][bcol0] = pb0.y;
                sB[nxt][akq + 2][bcol0] = pb0.z; sB[nxt][akq + 3][bcol0] = pb0.w;
                sB[nxt][akq + 0][bcol1] = pb1.x; sB[nxt][akq + 1][bcol1] = pb1.y;
                sB[nxt][akq + 2][bcol1] = pb1.z; sB[nxt][akq + 3][bcol1] = pb1.w;
            }
            __syncthreads();
        }

#pragma unroll
        for (int i = 0; i < 4; i++) {
            const float asq = Asq[bm + (ty << 2) + i];
            unsigned long long best = 0xFFFFFFFFFFFFFFFFULL;
#pragma unroll
            for (int j = 0; j < 8; j++) {
                const int col = bn + (tx << 3) + j;
                const float t1 = asq + cbsq[col];       // fl(A + B)
                const float d  = t1 - 2.0f * acc[i][j]; // fl(t1 - 2*dot), 2*dot exact
                unsigned long long p =
                    ((unsigned long long)__float_as_uint(d) << 32) | (unsigned)col;
                best = (p < best) ? p : best;
            }
            atomicMin(&sBest[(ty << 2) + i], best);
        }
        __syncthreads();
    }

    if (tid < 64) outIdx[bm + tid] = (int)(sBest[tid] & 0xFFFFFFFFu);
}

// ---------------- row sum of squares (one warp per 512-wide row) ----------------
__global__ void rowsumsq(const float* __restrict__ A, float* __restrict__ out, int rows)
{
    const int row = blockIdx.x * (blockDim.x >> 5) + (threadIdx.x >> 5);
    if (row >= rows) return;
    const int lane = threadIdx.x & 31;
    const float4* p = (const float4*)(A + (size_t)row * 512);
    float s = 0.f;
#pragma unroll
    for (int i = 0; i < 4; i++) {
        float4 v = p[lane + 32 * i];
        s += v.x * v.x; s += v.y * v.y; s += v.z * v.z; s += v.w * v.w;
    }
#pragma unroll
    for (int o = 16; o; o >>= 1) s += __shfl_xor_sync(0xffffffffu, s, o);
    if (!lane) out[row] = s;
}

// ---------------- residual = detail_feat - cb0[idx0] ----------------
__global__ void residual_kernel(const float* __restrict__ df,
                                const float* __restrict__ cb0,
                                const int* __restrict__ idx0,
                                float* __restrict__ res)
{
    const int row = blockIdx.x, t = threadIdx.x;  // 128 threads x float4
    const int id = idx0[row];
    float4 v = ((const float4*)(df  + (size_t)row * 512))[t];
    float4 q = ((const float4*)(cb0 + (size_t)id  * 512))[t];
    float4 r = make_float4(v.x - q.x, v.y - q.y, v.z - q.z, v.w - q.w);
    ((float4*)(res + (size_t)row * 512))[t] = r;
}

// ---------------- losses: 4 stages of sum((q - x)^2), deterministic ----------------
__global__ __launch_bounds__(256)
void loss_kernel(const float* __restrict__ tcb, const float* __restrict__ ecb,
                 const float* __restrict__ cb0, const float* __restrict__ cb1)
{
    double s = 0.0;
    const int total = NTOK * 128;  // float4 granules
    for (int i = blockIdx.x * 256 + threadIdx.x; i < total; i += 4096 * 256) {
        const int row = i >> 7, c = i & 127;
        float ps = 0.f;
        {
            float4 q = ((const float4*)(tcb + (size_t)g_idx[row] * 512))[c];
            float4 a = ((const float4*)(g_tf + (size_t)row * 512))[c];
            float dx = q.x - a.x, dy = q.y - a.y, dz = q.z - a.z, dw = q.w - a.w;
            ps += dx * dx + dy * dy + dz * dz + dw * dw;
        }
        {
            float4 q = ((const float4*)(ecb + (size_t)g_idx[NTOK + row] * 512))[c];
            float4 a = ((const float4*)(g_ef + (size_t)row * 512))[c];
            float dx = q.x - a.x, dy = q.y - a.y, dz = q.z - a.z, dw = q.w - a.w;
            ps += dx * dx + dy * dy + dz * dz + dw * dw;
        }
        {
            float4 q = ((const float4*)(cb0 + (size_t)g_idx[2 * NTOK + row] * 512))[c];
            float4 a = ((const float4*)(g_df + (size_t)row * 512))[c];
            float dx = q.x - a.x, dy = q.y - a.y, dz = q.z - a.z, dw = q.w - a.w;
            ps += dx * dx + dy * dy + dz * dz + dw * dw;
        }
        {
            float4 q = ((const float4*)(cb1 + (size_t)g_idx[3 * NTOK + row] * 512))[c];
            float4 a = ((const float4*)(g_res + (size_t)row * 512))[c];
            float dx = q.x - a.x, dy = q.y - a.y, dz = q.z - a.z, dw = q.w - a.w;
            ps += dx * dx + dy * dy + dz * dz + dw * dw;
        }
        s += (double)ps;
    }
    __shared__ double sh[256];
    sh[threadIdx.x] = s; __syncthreads();
    for (int o = 128; o; o >>= 1) {
        if (threadIdx.x < o) sh[threadIdx.x] += sh[threadIdx.x + o];
        __syncthreads();
    }
    if (!threadIdx.x) g_losspart[blockIdx.x] = sh[0];
}

__global__ void loss_final(float* __restrict__ out)
{
    __shared__ double sh[256];
    double s = 0.0;
    for (int i = threadIdx.x; i < 4096; i += 256) s += g_losspart[i];
    sh[threadIdx.x] = s; __syncthreads();
    for (int o = 128; o; o >>= 1) {
        if (threadIdx.x < o) sh[threadIdx.x] += sh[threadIdx.x + o];
        __syncthreads();
    }
    if (!threadIdx.x) out[0] = (float)(1.25 * sh[0] / (double)NQ);
}

// ---------------- final gather: out_b + Pt[ti] + Pe[ei] + P0[i0] + P1[i1] ----------------
__global__ void out_gather(const float* __restrict__ outb, float* __restrict__ out)
{
    const int row = blockIdx.x, t = threadIdx.x;  // 128 threads x float4
    const int it = g_idx[row];
    const int ie = g_idx[NTOK + row];
    const int i0 = g_idx[2 * NTOK + row];
    const int i1 = g_idx[3 * NTOK + row];
    float4 b  = ((const float4*)outb)[t];
    float4 a0 = ((const float4*)(g_P + (size_t)it * 512))[t];
    float4 a1 = ((const float4*)(g_P + (size_t)(512  + ie) * 512))[t];
    float4 a2 = ((const float4*)(g_P + (size_t)(768  + i0) * 512))[t];
    float4 a3 = ((const float4*)(g_P + (size_t)(1280 + i1) * 512))[t];
    float4 r = make_float4(b.x + a0.x + a1.x + a2.x + a3.x,
                           b.y + a0.y + a1.y + a2.y + a3.y,
                           b.z + a0.z + a1.z + a2.z + a3.z,
                           b.w + a0.w + a1.w + a2.w + a3.w);
    ((float4*)(out + (size_t)row * 512))[t] = r;
}

__global__ void write_idx(float* __restrict__ out)
{
    const int i = blockIdx.x * 256 + threadIdx.x;
    if (i < NTOK) {
        out[NQ + i]            = (float)g_idx[i];
        out[NQ + NTOK + i]     = (float)g_idx[NTOK + i];
        out[NQ + 2 * NTOK + i] = (float)g_idx[2 * NTOK + i];
        out[NQ + 3 * NTOK + i] = (float)g_idx[3 * NTOK + i];
    }
}

// =====================================================================
extern "C" void kernel_launch(void* const* d_in, const int* in_sizes, int n_in,
                              void* d_out, int out_size)
{
    const float* x   = (const float*)d_in[0];
    const float* tW  = (const float*)d_in[1];
    const float* tb  = (const float*)d_in[2];
    const float* eW  = (const float*)d_in[3];
    const float* eb  = (const float*)d_in[4];
    const float* dW  = (const float*)d_in[5];
    const float* db  = (const float*)d_in[6];
    const float* oW  = (const float*)d_in[7];
    const float* ob  = (const float*)d_in[8];
    const float* tcb = (const float*)d_in[9];
    const float* ecb = (const float*)d_in[10];
    const float* cb0 = (const float*)d_in[11];
    const float* cb1 = (const float*)d_in[12];
    float* out = (float*)d_out;

    void* p;
    cudaGetSymbolAddress(&p, g_tf);    float* tf   = (float*)p;
    cudaGetSymbolAddress(&p, g_ef);    float* ef   = (float*)p;
    cudaGetSymbolAddress(&p, g_df);    float* df   = (float*)p;
    cudaGetSymbolAddress(&p, g_res);   float* res  = (float*)p;
    cudaGetSymbolAddress(&p, g_sqA);   float* sqA  = (float*)p;
    cudaGetSymbolAddress(&p, g_cbsq);  float* cbsq = (float*)p;
    cudaGetSymbolAddress(&p, g_idx);   int*   idx  = (int*)p;
    cudaGetSymbolAddress(&p, g_P);     float* P    = (float*)p;

    // 1) feature linears (fp32, matches reference rounding class)
    dim3 gFeat(4, 1024);
    gemm_nt<<<gFeat, 256>>>(x, 512, tW, 512, tb, tf, 512, 512);
    gemm_nt<<<gFeat, 256>>>(x, 512, eW, 512, eb, ef, 512, 512);
    gemm_nt<<<gFeat, 256>>>(x, 512, dW, 512, db, df, 512, 512);

    // 2) sums of squares
    rowsumsq<<<8192, 256>>>(tf, sqA,            NTOK);
    rowsumsq<<<8192, 256>>>(ef, sqA + NTOK,     NTOK);
    rowsumsq<<<8192, 256>>>(df, sqA + 2 * NTOK, NTOK);
    rowsumsq<<<64, 256>>>(tcb, cbsq,        512);
    rowsumsq<<<32, 256>>>(ecb, cbsq + 512,  256);
    rowsumsq<<<64, 256>>>(cb0, cbsq + 768,  512);
    rowsumsq<<<64, 256>>>(cb1, cbsq + 1280, 512);

    // 3) VQ argmins
    vq_argmin<<<1024, 256>>>(tf, sqA,            tcb, cbsq,        512, idx);
    vq_argmin<<<1024, 256>>>(ef, sqA + NTOK,     ecb, cbsq + 512,  256, idx + NTOK);
    vq_argmin<<<1024, 256>>>(df, sqA + 2 * NTOK, cb0, cbsq + 768,  512, idx + 2 * NTOK);

    // 4) residual stage
    residual_kernel<<<NTOK, 128>>>(df, cb0, idx + 2 * NTOK, res);
    rowsumsq<<<8192, 256>>>(res, sqA + 3 * NTOK, NTOK);
    vq_argmin<<<1024, 256>>>(res, sqA + 3 * NTOK, cb1, cbsq + 1280, 512, idx + 3 * NTOK);

    // 5) loss (deterministic 2-stage double reduction)
    loss_kernel<<<4096, 256>>>(tcb, ecb, cb0, cb1);
    loss_final<<<1, 256>>>(out + NQ + 4 * NTOK);

    // 6) projected codebooks through out_W slices (replaces 103 GF output GEMM)
    gemm_nt<<<dim3(4, 8), 256>>>(tcb, 512, oW,        1536, nullptr, P,              512, 512);
    gemm_nt<<<dim3(4, 4), 256>>>(ecb, 512, oW + 512,  1536, nullptr, P + 512  * 512, 512, 512);
    gemm_nt<<<dim3(4, 8), 256>>>(cb0, 512, oW + 1024, 1536, nullptr, P + 768  * 512, 512, 512);
    gemm_nt<<<dim3(4, 8), 256>>>(cb1, 512, oW + 1024, 1536, nullptr, P + 1280 * 512, 512, 512);

    // 7) outputs
    out_gather<<<NTOK, 128>>>(ob, out);
    write_idx<<<256, 256>>>(out);
}